// round 10
// baseline (speedup 1.0000x reference)
#include <cuda_runtime.h>

#define N_BINS 10
#define GRID_BLOCKS 888        // 148 SMs * 6 blocks
#define BLOCK_THREADS 128
#define WPB 4                  // warps per block
#define TOTAL_WARPS (GRID_BLOCKS * WPB)
#define TILE_ROWS 16           // rows per warp-tile

// Global scratch (no allocations allowed). Zero-initialized at module load;
// the last finishing block resets them, so "zeroed at entry" holds across
// graph replays.
__device__ double g_cnt[N_BINS];
__device__ double g_conf[N_BINS];
__device__ double g_acc[N_BINS];
__device__ unsigned g_done;

// Raw ex2; used identically at both exp sites so recomputation is bit-exact.
__device__ __forceinline__ float expf_raw(float x) {
    float t = __fmul_rn(x, 1.4426950408889634f);
    float r;
    asm("ex2.approx.f32 %0, %1;" : "=f"(r) : "f"(t));
    return r;
}

__global__ void __launch_bounds__(BLOCK_THREADS) ece_fused(
    const float* __restrict__ logits,
    const int* __restrict__ labels,
    int n_rows,
    float* __restrict__ out)
{
    // Per-warp tile: 16 rows x 32 float4 (8KB), XOR-swizzled:
    // row r, chunk c stored at [r][c ^ (r & 7)]. Conflict-free for both the
    // row-broadcast STS and the per-thread strided LDS.
    __shared__ float4 tile[WPB][TILE_ROWS][32];
    __shared__ float s_c[N_BINS], s_f[N_BINS], s_a[N_BINS];

    const int tid  = threadIdx.x;
    if (tid < N_BINS) { s_c[tid] = 0.0f; s_f[tid] = 0.0f; s_a[tid] = 0.0f; }
    __syncthreads();

    const int lane  = tid & 31;
    const int warp  = tid >> 5;
    const int r     = lane & 15;        // my row within the tile
    const int half  = lane >> 4;        // 0: cols 0-63, 1: cols 64-127
    const int gwarp = blockIdx.x * WPB + warp;

    const float4* __restrict__ lrows = (const float4*)logits;
    float4 (* __restrict__ T)[32] = tile[warp];
    const float* __restrict__ Ts = (const float*)tile[warp];   // scalar view

    const int n_tiles = (n_rows + TILE_ROWS - 1) / TILE_ROWS;

    for (int t = gwarp; t < n_tiles; t += TOTAL_WARPS) {
        const int base = t * TILE_ROWS;

        // ---- Load phase: 16 coalesced rows -> swizzled smem ----
        const float4* src = lrows + (size_t)base * 32 + lane;
        #pragma unroll
        for (int i = 0; i < TILE_ROWS; i++) {
            float4 v = (base + i < n_rows) ? src[i * 32]
                                           : make_float4(0.f, 0.f, 0.f, 0.f);
            T[i][lane ^ (i & 7)] = v;
        }
        // Label for my row (clamped; unused lanes/rows guarded later).
        int lab = labels[min(base + r, n_rows - 1)];
        __syncwarp();

        // ---- Compute phase: scalar scan of my half-row (no collectives) ----
        float sA = 0.0f, sB = 0.0f, mx = 0.0f;   // exps > 0, so 0 works as -inf
        const int rx = r & 7;
        #pragma unroll
        for (int j = 0; j < 16; j++) {
            float4 v = T[r][(half << 4) | (j ^ rx)];
            float e0 = expf_raw(v.x), e1 = expf_raw(v.y);
            float e2 = expf_raw(v.z), e3 = expf_raw(v.w);
            sA += e0 + e1;
            sB += e2 + e3;
            mx = fmaxf(mx, fmaxf(fmaxf(e0, e1), fmaxf(e2, e3)));
        }
        float s = sA + sB;

        // Combine the two half-rows (one shfl pair per tile).
        s  += __shfl_xor_sync(0xffffffffu, s, 16);
        float om = __shfl_xor_sync(0xffffffffu, mx, 16);
        mx = fmaxf(mx, om);

        if (half == 0 && base + r < n_rows) {
            // exp at the label column: scalar smem read + bit-exact recompute.
            int c4 = (lab >> 2) & 31;
            float lv = Ts[(r * 32 + (c4 ^ rx)) * 4 + (lab & 3)];
            float le = expf_raw(lv);

            float conf = __fdividef(mx, s);
            int b = min((int)ceilf(conf * 10.0f), N_BINS) - 1;
            b = max(b, 0);
            atomicAdd(&s_c[b], 1.0f);
            atomicAdd(&s_f[b], conf);
            atomicAdd(&s_a[b], (le == mx) ? 1.0f : 0.0f);
        }
        __syncwarp();   // protect smem tile before next iteration's stores
    }

    // ---- Block -> global reduction ----
    __syncthreads();
    if (tid < N_BINS) {
        atomicAdd(&g_cnt[tid],  (double)s_c[tid]);
        atomicAdd(&g_conf[tid], (double)s_f[tid]);
        atomicAdd(&g_acc[tid],  (double)s_a[tid]);
        __threadfence();               // order bin atomics before done-ticket
    }
    __syncthreads();

    // Last block finalizes and resets scratch for the next graph replay.
    if (tid == 0) {
        unsigned ticket = atomicAdd(&g_done, 1u);
        if (ticket == GRID_BLOCKS - 1) {
            double ece = 0.0, oe = 0.0;
            #pragma unroll
            for (int i = 0; i < N_BINS; i++) {
                double cnt = atomicAdd(&g_cnt[i],  0.0);
                double cf  = atomicAdd(&g_conf[i], 0.0);
                double ac  = atomicAdd(&g_acc[i],  0.0);
                bool nonempty = cnt > 0.0;
                double prop  = cnt / (double)n_rows;
                double denom = nonempty ? cnt : 1.0;
                double accb  = nonempty ? ac / denom : 0.0;
                double cfb   = nonempty ? cf / denom : 0.0;
                double CE    = cfb - accb;
                double absCE = nonempty ? fabs(CE) : 0.0;
                ece += absCE * prop;
                oe  += (nonempty ? cfb * fmax(CE, 0.0) : 0.0) * prop;
                out[1 + i]  = (float)accb;
                out[12 + i] = (float)prop;
                out[22 + i] = (float)absCE;
                g_cnt[i] = 0.0; g_conf[i] = 0.0; g_acc[i] = 0.0;
            }
            out[0]  = (float)ece;
            out[11] = (float)oe;
            g_done = 0u;
            __threadfence();
        }
    }
}

extern "C" void kernel_launch(void* const* d_in, const int* in_sizes, int n_in,
                              void* d_out, int out_size) {
    const float* logits = (const float*)d_in[0];
    const int*   labels = (const int*)d_in[1];
    float*       out    = (float*)d_out;

    int n_rows = in_sizes[0] / 128;   // C = 128

    ece_fused<<<GRID_BLOCKS, BLOCK_THREADS>>>(logits, labels, n_rows, out);
}